// round 7
// baseline (speedup 1.0000x reference)
#include <cuda_runtime.h>

#define NN 50000
#define EE 800000
#define ET (EE + NN)
#define NEG_SLOPE 0.2f
#define FULLMASK 0xFFFFFFFFu
#define SCAN_B 1024
#define NBLK ((NN + SCAN_B - 1) / SCAN_B)   // 49

// -------- scratch (static __device__ — no allocations allowed) --------
__device__ float  g_h[NN * 64];
__device__ float  g_x2[NN * 64];
__device__ float  g_as[NN];
__device__ float  g_ad[NN];
__device__ float4 g_nst[NN];        // {ad, m, inv, unused} per node
__device__ int    g_cnt[NN];
__device__ int    g_off[NN + 1];
__device__ int    g_cur[NN];
__device__ int    g_csr[ET];        // src per CSR slot
__device__ int    g_dstc[ET];       // dst per CSR slot
__device__ int2   g_sw[ET];         // {src, float_bits(normalized w)} per slot
__device__ int    g_blksum[NBLK];
__device__ int    g_is64;

// host-side stream/event for graph fork
static cudaStream_t g_s2;
static cudaEvent_t  g_evF, g_evJ;
static struct StreamInit {
    StreamInit() {
        cudaStreamCreateWithFlags(&g_s2, cudaStreamNonBlocking);
        cudaEventCreateWithFlags(&g_evF, cudaEventDisableTiming);
        cudaEventCreateWithFlags(&g_evJ, cudaEventDisableTiming);
    }
} g_stream_init;

// -------- dtype detection --------
__global__ void detect_dtype(const int* __restrict__ ei32) {
    int any = 0;
    for (int i = threadIdx.x; i < 1024; i += 256)
        if (ei32[2 * i + 1] != 0) any = 1;
    int nz = __syncthreads_or(any);
    if (threadIdx.x == 0) g_is64 = nz ? 0 : 1;
}

// -------- CSR construction (2 edges per thread, vector loads) --------
__global__ void hist2(const void* __restrict__ ei) {
    int i2 = blockIdx.x * blockDim.x + threadIdx.x;
    int i0 = i2 * 2;
    if (i0 >= ET) return;
    int d0, d1;
    if (i0 >= EE) {                       // both are self-loops (EE even)
        d0 = i0 - EE; d1 = i0 + 1 - EE;
    } else if (g_is64) {
        longlong2 dd = ((const longlong2*)((const long long*)ei + EE))[i2];
        d0 = (int)dd.x; d1 = (int)dd.y;
    } else {
        int2 dd = ((const int2*)((const int*)ei + EE))[i2];
        d0 = dd.x; d1 = dd.y;
    }
    atomicAdd(&g_cnt[d0], 1);
    atomicAdd(&g_cnt[d1], 1);
}

__global__ void scan_block() {
    __shared__ int sh[SCAN_B];
    int t = threadIdx.x;
    int i = blockIdx.x * SCAN_B + t;
    int v = (i < NN) ? g_cnt[i] : 0;
    sh[t] = v;
    __syncthreads();
#pragma unroll
    for (int o = 1; o < SCAN_B; o <<= 1) {
        int add = (t >= o) ? sh[t - o] : 0;
        __syncthreads();
        sh[t] += add;
        __syncthreads();
    }
    if (i < NN) g_off[i] = sh[t] - v;
    if (t == SCAN_B - 1) g_blksum[blockIdx.x] = sh[t];
}

__global__ void scan_tops() {
    int t = threadIdx.x;
    __shared__ int sh[NBLK];
    if (t < NBLK) sh[t] = g_blksum[t];
    __syncthreads();
    if (t == 0) {
        int run = 0;
        for (int i = 0; i < NBLK; i++) { int v = sh[i]; sh[i] = run; run += v; }
        g_off[NN] = run;
    }
    __syncthreads();
    if (t < NBLK) g_blksum[t] = sh[t];
}

__global__ void scan_add() {
    int i = blockIdx.x * blockDim.x + threadIdx.x;
    if (i >= NN) return;
    int v = g_off[i] + g_blksum[i / SCAN_B];
    g_off[i] = v;
    g_cur[i] = v;
}

__global__ void scatter2(const void* __restrict__ ei) {
    int i2 = blockIdx.x * blockDim.x + threadIdx.x;
    int i0 = i2 * 2;
    if (i0 >= ET) return;
    int s0, s1, d0, d1;
    if (i0 >= EE) {
        s0 = d0 = i0 - EE; s1 = d1 = i0 + 1 - EE;
    } else if (g_is64) {
        longlong2 ss = ((const longlong2*)ei)[i2];
        longlong2 dd = ((const longlong2*)((const long long*)ei + EE))[i2];
        s0 = (int)ss.x; s1 = (int)ss.y; d0 = (int)dd.x; d1 = (int)dd.y;
    } else {
        int2 ss = ((const int2*)ei)[i2];
        int2 dd = ((const int2*)((const int*)ei + EE))[i2];
        s0 = ss.x; s1 = ss.y; d0 = dd.x; d1 = dd.y;
    }
    int p0 = atomicAdd(&g_cur[d0], 1);
    g_csr[p0] = s0; g_dstc[p0] = d0;
    int p1 = atomicAdd(&g_cur[d1], 1);
    g_csr[p1] = s1; g_dstc[p1] = d1;
}

// -------- GEMM + attention-logit fusion (32 nodes/block, 512 threads) ------
template <int FIN, bool USE_X2>
__global__ void gemm_alpha(const float* __restrict__ xin,
                           const float* __restrict__ W,
                           const float* __restrict__ a_src,
                           const float* __restrict__ a_dst) {
    __shared__ float sW[FIN * 64];
    __shared__ float sX[32 * FIN];

    const float* x = USE_X2 ? g_x2 : xin;
    int t = threadIdx.x;
    int node0 = blockIdx.x * 32;

    for (int i = t; i < FIN * 16; i += 512)
        ((float4*)sW)[i] = ((const float4*)W)[i];
    for (int i = t; i < 8 * FIN; i += 512) {
        int n = node0 + i / (FIN / 4);
        ((float4*)sX)[i] = (n < NN) ? ((const float4*)x)[(long)n * (FIN / 4) + (i % (FIN / 4))]
                                    : make_float4(0.f, 0.f, 0.f, 0.f);
    }
    __syncthreads();

    int node = t >> 4;
    int f4   = t & 15;
    float4 acc = make_float4(0.f, 0.f, 0.f, 0.f);

#pragma unroll 4
    for (int k = 0; k < FIN; k += 4) {
        float4 xv = *(const float4*)&sX[node * FIN + k];
#pragma unroll
        for (int i = 0; i < 4; i++) {
            float xk = (i == 0) ? xv.x : (i == 1) ? xv.y : (i == 2) ? xv.z : xv.w;
            float4 wv = *(const float4*)&sW[(k + i) * 64 + f4 * 4];
            acc.x = fmaf(xk, wv.x, acc.x);
            acc.y = fmaf(xk, wv.y, acc.y);
            acc.z = fmaf(xk, wv.z, acc.z);
            acc.w = fmaf(xk, wv.w, acc.w);
        }
    }

    int n = node0 + node;
    if (n < NN)
        *(float4*)&g_h[(long)n * 64 + f4 * 4] = acc;

    float4 as4 = ((const float4*)a_src)[f4];
    float4 ad4 = ((const float4*)a_dst)[f4];
    float s1 = acc.x * as4.x + acc.y * as4.y + acc.z * as4.z + acc.w * as4.w;
    float s2 = acc.x * ad4.x + acc.y * ad4.y + acc.z * ad4.z + acc.w * ad4.w;
#pragma unroll
    for (int o = 8; o > 0; o >>= 1) {
        s1 += __shfl_down_sync(FULLMASK, s1, o, 16);
        s2 += __shfl_down_sync(FULLMASK, s2, o, 16);
    }
    if (f4 == 0 && n < NN) {
        g_as[n] = s1;
        g_ad[n] = s2;
    }
}

// -------- stats: warp per node, online softmax -> {ad, m, inv} --------
__global__ void gat_stats() {
    int gw   = (blockIdx.x * blockDim.x + threadIdx.x) >> 5;
    int lane = threadIdx.x & 31;
    if (gw >= NN) return;
    int n   = gw;
    int off = g_off[n];
    int end = g_off[n + 1];
    float ad_n = g_ad[n];

    float m = -1e30f, ssum = 0.0f;
    for (int e = off + lane; e < end; e += 32) {
        int s = g_csr[e];
        float v = g_as[s] + ad_n;
        v = (v > 0.0f) ? v : NEG_SLOPE * v;
        if (v <= m) {
            ssum += __expf(v - m);
        } else {
            ssum = ssum * __expf(m - v) + 1.0f;
            m = v;
        }
    }
#pragma unroll
    for (int o = 16; o > 0; o >>= 1) {
        float m2 = __shfl_down_sync(FULLMASK, m, o);
        float s2 = __shfl_down_sync(FULLMASK, ssum, o);
        float M = fmaxf(m, m2);
        ssum = ssum * __expf(m - M) + s2 * __expf(m2 - M);
        m = M;
    }
    if (lane == 0)
        g_nst[n] = make_float4(ad_n, m, 1.0f / (ssum + 1e-16f), 0.0f);
}

// -------- edge-parallel normalized weight computation --------
__global__ void edge_w() {
    int e = blockIdx.x * blockDim.x + threadIdx.x;
    if (e >= ET) return;
    int s = g_csr[e];
    int d = g_dstc[e];
    float4 st = g_nst[d];             // {ad, m, inv}
    float v = g_as[s] + st.x;
    v = (v > 0.0f) ? v : NEG_SLOPE * v;
    float w = __expf(v - st.y) * st.z;
    g_sw[e] = make_int2(s, __float_as_int(w));
}

// -------- aggregation: 2 warps per node, smem combine --------
template <bool LAYER2>
__global__ void gat_agg(const float* __restrict__ b, float* __restrict__ out) {
    __shared__ float sacc[4][64];     // 4 nodes per 256-thread block
    int t    = threadIdx.x;
    int w    = t >> 5;                // 0..7
    int lane = t & 31;
    int nl   = w >> 1;                // node-local 0..3
    int half = w & 1;
    int n    = blockIdx.x * 4 + nl;

    // zero shared
    ((float*)sacc)[t] = 0.0f;
    __syncthreads();

    if (n < NN) {
        int off = g_off[n];
        int end = g_off[n + 1];
        float accx = 0.0f, accy = 0.0f;

        int e = off + half;           // stride-2 split between the 2 warps
        for (; e + 6 < end; e += 8) {
            int2 p0 = g_sw[e],     p1 = g_sw[e + 2];
            int2 p2 = g_sw[e + 4], p3 = g_sw[e + 6];
            float2 h0 = *(const float2*)(g_h + (long)p0.x * 64 + lane * 2);
            float2 h1 = *(const float2*)(g_h + (long)p1.x * 64 + lane * 2);
            float2 h2 = *(const float2*)(g_h + (long)p2.x * 64 + lane * 2);
            float2 h3 = *(const float2*)(g_h + (long)p3.x * 64 + lane * 2);
            float w0 = __int_as_float(p0.y), w1 = __int_as_float(p1.y);
            float w2 = __int_as_float(p2.y), w3 = __int_as_float(p3.y);
            accx = fmaf(w0, h0.x, accx); accy = fmaf(w0, h0.y, accy);
            accx = fmaf(w1, h1.x, accx); accy = fmaf(w1, h1.y, accy);
            accx = fmaf(w2, h2.x, accx); accy = fmaf(w2, h2.y, accy);
            accx = fmaf(w3, h3.x, accx); accy = fmaf(w3, h3.y, accy);
        }
        for (; e < end; e += 2) {
            int2 p0 = g_sw[e];
            float2 h0 = *(const float2*)(g_h + (long)p0.x * 64 + lane * 2);
            float w0 = __int_as_float(p0.y);
            accx = fmaf(w0, h0.x, accx);
            accy = fmaf(w0, h0.y, accy);
        }
        atomicAdd(&sacc[nl][lane * 2],     accx);
        atomicAdd(&sacc[nl][lane * 2 + 1], accy);
    }
    __syncthreads();

    // write out: thread t handles node t>>6, feature t&63
    int no = blockIdx.x * 4 + (t >> 6);
    if (no < NN) {
        int f = t & 63;
        float v = sacc[t >> 6][f] + b[f];
        long idx = (long)no * 64 + f;
        if (!LAYER2) g_x2[idx] = fmaxf(v, 0.0f);
        else         out[idx]  = v;
    }
}

extern "C" void kernel_launch(void* const* d_in, const int* in_sizes, int n_in,
                              void* d_out, int out_size) {
    const float* x   = (const float*)d_in[0];
    const void*  ei  = d_in[1];
    const float* W1  = (const float*)d_in[2];
    const float* a1s = (const float*)d_in[3];
    const float* a1d = (const float*)d_in[4];
    const float* b1  = (const float*)d_in[5];
    const float* W2  = (const float*)d_in[6];
    const float* a2s = (const float*)d_in[7];
    const float* a2d = (const float*)d_in[8];
    const float* b2  = (const float*)d_in[9];
    float* out = (float*)d_out;

    const int TB = 256;
    const int gNodes = (NN + 31) / 32;
    const int gEdge2 = (ET / 2 + TB - 1) / TB;
    const int gEdge  = (ET + TB - 1) / TB;
    const int gN     = (NN + TB - 1) / TB;
    const int gWarp  = (NN * 32 + TB - 1) / TB;
    const int gAgg   = (NN + 3) / 4;

    void* cntp;
    cudaGetSymbolAddress(&cntp, g_cnt);   // resolves at first call; host-side only

    // fork: layer-1 GEMM concurrent with CSR build
    cudaEventRecord(g_evF, 0);
    cudaStreamWaitEvent(g_s2, g_evF, 0);
    gemm_alpha<128, false><<<gNodes, 512, 0, g_s2>>>(x, W1, a1s, a1d);

    detect_dtype<<<1, 256>>>((const int*)ei);
    cudaMemsetAsync(cntp, 0, NN * sizeof(int), 0);
    hist2<<<gEdge2, TB>>>(ei);
    scan_block<<<NBLK, SCAN_B>>>();
    scan_tops<<<1, 64>>>();
    scan_add<<<gN, TB>>>();
    scatter2<<<gEdge2, TB>>>(ei);

    cudaEventRecord(g_evJ, g_s2);
    cudaStreamWaitEvent(0, g_evJ, 0);

    // ---- layer 1 ----
    gat_stats<<<gWarp, TB>>>();
    edge_w<<<gEdge, TB>>>();
    gat_agg<false><<<gAgg, TB>>>(b1, nullptr);

    // ---- layer 2 ----
    gemm_alpha<64, true><<<gNodes, 512>>>(nullptr, W2, a2s, a2d);
    gat_stats<<<gWarp, TB>>>();
    edge_w<<<gEdge, TB>>>();
    gat_agg<true><<<gAgg, TB>>>(b2, out);
}

// round 8
// speedup vs baseline: 1.2816x; 1.2816x over previous
#include <cuda_runtime.h>

#define NN 50000
#define EE 800000
#define ET (EE + NN)
#define NEG_SLOPE 0.2f
#define FULLMASK 0xFFFFFFFFu
#define SCAN_B 1024
#define NBLK ((NN + SCAN_B - 1) / SCAN_B)   // 49
#define DEGCAP 128

// -------- scratch (static __device__ — no allocations allowed) --------
__device__ float g_h[NN * 64];
__device__ float g_x2[NN * 64];
__device__ float g_as[NN];
__device__ float g_ad[NN];
__device__ int   g_cnt[NN];
__device__ int   g_off[NN + 1];
__device__ int   g_cur[NN];
__device__ int   g_csr[ET];
__device__ int   g_blksum[NBLK];
__device__ int   g_is64;

// host-side stream/event for graph fork
static cudaStream_t g_s2;
static cudaEvent_t  g_evF, g_evJ;
static struct StreamInit {
    StreamInit() {
        cudaStreamCreateWithFlags(&g_s2, cudaStreamNonBlocking);
        cudaEventCreateWithFlags(&g_evF, cudaEventDisableTiming);
        cudaEventCreateWithFlags(&g_evJ, cudaEventDisableTiming);
    }
} g_stream_init;

// -------- dtype detection --------
__global__ void detect_dtype(const int* __restrict__ ei32) {
    int any = 0;
    for (int i = threadIdx.x; i < 1024; i += 256)
        if (ei32[2 * i + 1] != 0) any = 1;
    int nz = __syncthreads_or(any);
    if (threadIdx.x == 0) g_is64 = nz ? 0 : 1;
}

// -------- CSR construction (2 edges per thread, vector loads) --------
__global__ void hist2(const void* __restrict__ ei) {
    int i2 = blockIdx.x * blockDim.x + threadIdx.x;
    int i0 = i2 * 2;
    if (i0 >= ET) return;
    int d0, d1;
    if (i0 >= EE) {                       // EE even -> both self-loops
        d0 = i0 - EE; d1 = i0 + 1 - EE;
    } else if (g_is64) {
        longlong2 dd = ((const longlong2*)((const long long*)ei + EE))[i2];
        d0 = (int)dd.x; d1 = (int)dd.y;
    } else {
        int2 dd = ((const int2*)((const int*)ei + EE))[i2];
        d0 = dd.x; d1 = dd.y;
    }
    atomicAdd(&g_cnt[d0], 1);
    atomicAdd(&g_cnt[d1], 1);
}

__global__ void scan_block() {
    __shared__ int sh[SCAN_B];
    int t = threadIdx.x;
    int i = blockIdx.x * SCAN_B + t;
    int v = (i < NN) ? g_cnt[i] : 0;
    sh[t] = v;
    __syncthreads();
#pragma unroll
    for (int o = 1; o < SCAN_B; o <<= 1) {
        int add = (t >= o) ? sh[t - o] : 0;
        __syncthreads();
        sh[t] += add;
        __syncthreads();
    }
    if (i < NN) g_off[i] = sh[t] - v;
    if (t == SCAN_B - 1) g_blksum[blockIdx.x] = sh[t];
}

__global__ void scan_tops() {
    int t = threadIdx.x;
    __shared__ int sh[NBLK];
    if (t < NBLK) sh[t] = g_blksum[t];
    __syncthreads();
    if (t == 0) {
        int run = 0;
        for (int i = 0; i < NBLK; i++) { int v = sh[i]; sh[i] = run; run += v; }
        g_off[NN] = run;
    }
    __syncthreads();
    if (t < NBLK) g_blksum[t] = sh[t];
}

__global__ void scan_add() {
    int i = blockIdx.x * blockDim.x + threadIdx.x;
    if (i >= NN) return;
    int v = g_off[i] + g_blksum[i / SCAN_B];
    g_off[i] = v;
    g_cur[i] = v;
}

__global__ void scatter2(const void* __restrict__ ei) {
    int i2 = blockIdx.x * blockDim.x + threadIdx.x;
    int i0 = i2 * 2;
    if (i0 >= ET) return;
    int s0, s1, d0, d1;
    if (i0 >= EE) {
        s0 = d0 = i0 - EE; s1 = d1 = i0 + 1 - EE;
    } else if (g_is64) {
        longlong2 ss = ((const longlong2*)ei)[i2];
        longlong2 dd = ((const longlong2*)((const long long*)ei + EE))[i2];
        s0 = (int)ss.x; s1 = (int)ss.y; d0 = (int)dd.x; d1 = (int)dd.y;
    } else {
        int2 ss = ((const int2*)ei)[i2];
        int2 dd = ((const int2*)((const int*)ei + EE))[i2];
        s0 = ss.x; s1 = ss.y; d0 = dd.x; d1 = dd.y;
    }
    int p0 = atomicAdd(&g_cur[d0], 1);
    g_csr[p0] = s0;
    int p1 = atomicAdd(&g_cur[d1], 1);
    g_csr[p1] = s1;
}

// -------- GEMM + attention-logit fusion (32 nodes/block, 512 threads) ------
template <int FIN, bool USE_X2>
__global__ void gemm_alpha(const float* __restrict__ xin,
                           const float* __restrict__ W,
                           const float* __restrict__ a_src,
                           const float* __restrict__ a_dst) {
    __shared__ float sW[FIN * 64];
    __shared__ float sX[32 * FIN];

    const float* x = USE_X2 ? g_x2 : xin;
    int t = threadIdx.x;
    int node0 = blockIdx.x * 32;

    for (int i = t; i < FIN * 16; i += 512)
        ((float4*)sW)[i] = ((const float4*)W)[i];
    for (int i = t; i < 8 * FIN; i += 512) {
        int n = node0 + i / (FIN / 4);
        ((float4*)sX)[i] = (n < NN) ? ((const float4*)x)[(long)n * (FIN / 4) + (i % (FIN / 4))]
                                    : make_float4(0.f, 0.f, 0.f, 0.f);
    }
    __syncthreads();

    int node = t >> 4;
    int f4   = t & 15;
    float4 acc = make_float4(0.f, 0.f, 0.f, 0.f);

#pragma unroll 4
    for (int k = 0; k < FIN; k += 4) {
        float4 xv = *(const float4*)&sX[node * FIN + k];
#pragma unroll
        for (int i = 0; i < 4; i++) {
            float xk = (i == 0) ? xv.x : (i == 1) ? xv.y : (i == 2) ? xv.z : xv.w;
            float4 wv = *(const float4*)&sW[(k + i) * 64 + f4 * 4];
            acc.x = fmaf(xk, wv.x, acc.x);
            acc.y = fmaf(xk, wv.y, acc.y);
            acc.z = fmaf(xk, wv.z, acc.z);
            acc.w = fmaf(xk, wv.w, acc.w);
        }
    }

    int n = node0 + node;
    if (n < NN)
        *(float4*)&g_h[(long)n * 64 + f4 * 4] = acc;

    float4 as4 = ((const float4*)a_src)[f4];
    float4 ad4 = ((const float4*)a_dst)[f4];
    float s1 = acc.x * as4.x + acc.y * as4.y + acc.z * as4.z + acc.w * as4.w;
    float s2 = acc.x * ad4.x + acc.y * ad4.y + acc.z * ad4.z + acc.w * ad4.w;
#pragma unroll
    for (int o = 8; o > 0; o >>= 1) {
        s1 += __shfl_down_sync(FULLMASK, s1, o, 16);
        s2 += __shfl_down_sync(FULLMASK, s2, o, 16);
    }
    if (f4 == 0 && n < NN) {
        g_as[n] = s1;
        g_ad[n] = s2;
    }
}

// -------- fused per-node softmax + aggregation, smem-cached logits --------
// warp per node; per-warp staging of (src, weight) in shared memory.
template <bool LAYER2>
__global__ void gat_node(const float* __restrict__ b, float* __restrict__ out) {
    __shared__ int   sS[8][DEGCAP];
    __shared__ float sV[8][DEGCAP];

    int w    = threadIdx.x >> 5;
    int lane = threadIdx.x & 31;
    int n    = blockIdx.x * 8 + w;
    if (n >= NN) return;

    int off = g_off[n];
    int end = g_off[n + 1];
    int deg = end - off;
    float ad_n = g_ad[n];
    float accx = 0.0f, accy = 0.0f;
    float inv;

    if (deg <= DEGCAP) {
        // pass 1a: load, compute logits into smem, track max
        float m = -1e30f;
        for (int j = lane; j < deg; j += 32) {
            int s = g_csr[off + j];
            float v = g_as[s] + ad_n;
            v = (v > 0.0f) ? v : NEG_SLOPE * v;
            sS[w][j] = s;
            sV[w][j] = v;
            m = fmaxf(m, v);
        }
#pragma unroll
        for (int o = 16; o > 0; o >>= 1)
            m = fmaxf(m, __shfl_xor_sync(FULLMASK, m, o));

        // pass 1b: exp in-place, sum
        float ssum = 0.0f;
        for (int j = lane; j < deg; j += 32) {
            float wt = __expf(sV[w][j] - m);
            sV[w][j] = wt;
            ssum += wt;
        }
#pragma unroll
        for (int o = 16; o > 0; o >>= 1)
            ssum += __shfl_xor_sync(FULLMASK, ssum, o);
        inv = 1.0f / (ssum + 1e-16f);
        __syncwarp();

        // pass 2: pure h-gather, weights from smem (broadcast)
        int j = 0;
        for (; j + 4 <= deg; j += 4) {
            int   s0 = sS[w][j],     s1 = sS[w][j + 1];
            int   s2 = sS[w][j + 2], s3 = sS[w][j + 3];
            float w0 = sV[w][j],     w1 = sV[w][j + 1];
            float w2 = sV[w][j + 2], w3 = sV[w][j + 3];
            float2 h0 = *(const float2*)(g_h + (long)s0 * 64 + lane * 2);
            float2 h1 = *(const float2*)(g_h + (long)s1 * 64 + lane * 2);
            float2 h2 = *(const float2*)(g_h + (long)s2 * 64 + lane * 2);
            float2 h3 = *(const float2*)(g_h + (long)s3 * 64 + lane * 2);
            accx = fmaf(w0, h0.x, accx); accy = fmaf(w0, h0.y, accy);
            accx = fmaf(w1, h1.x, accx); accy = fmaf(w1, h1.y, accy);
            accx = fmaf(w2, h2.x, accx); accy = fmaf(w2, h2.y, accy);
            accx = fmaf(w3, h3.x, accx); accy = fmaf(w3, h3.y, accy);
        }
        for (; j < deg; j++) {
            int   s0 = sS[w][j];
            float w0 = sV[w][j];
            float2 h0 = *(const float2*)(g_h + (long)s0 * 64 + lane * 2);
            accx = fmaf(w0, h0.x, accx);
            accy = fmaf(w0, h0.y, accy);
        }
    } else {
        // fallback (degree > DEGCAP): online softmax + recompute (R6 path)
        float m = -1e30f, ssum = 0.0f;
        for (int e = off + lane; e < end; e += 32) {
            int s = g_csr[e];
            float v = g_as[s] + ad_n;
            v = (v > 0.0f) ? v : NEG_SLOPE * v;
            if (v <= m) {
                ssum += __expf(v - m);
            } else {
                ssum = ssum * __expf(m - v) + 1.0f;
                m = v;
            }
        }
#pragma unroll
        for (int o = 16; o > 0; o >>= 1) {
            float m2 = __shfl_down_sync(FULLMASK, m, o);
            float s2 = __shfl_down_sync(FULLMASK, ssum, o);
            float M = fmaxf(m, m2);
            ssum = ssum * __expf(m - M) + s2 * __expf(m2 - M);
            m = M;
        }
        m    = __shfl_sync(FULLMASK, m, 0);
        ssum = __shfl_sync(FULLMASK, ssum, 0);
        inv  = 1.0f / (ssum + 1e-16f);

        for (int e = off; e < end; e++) {
            int s0 = g_csr[e];
            float v0 = g_as[s0] + ad_n;
            v0 = (v0 > 0.0f) ? v0 : NEG_SLOPE * v0;
            float w0 = __expf(v0 - m);
            float2 h0 = *(const float2*)(g_h + (long)s0 * 64 + lane * 2);
            accx = fmaf(w0, h0.x, accx);
            accy = fmaf(w0, h0.y, accy);
        }
    }

    float ox = accx * inv + b[lane * 2];
    float oy = accy * inv + b[lane * 2 + 1];
    long idx = (long)n * 64 + lane * 2;
    if (!LAYER2) {
        g_x2[idx]     = fmaxf(ox, 0.0f);
        g_x2[idx + 1] = fmaxf(oy, 0.0f);
    } else {
        out[idx]     = ox;
        out[idx + 1] = oy;
    }
}

extern "C" void kernel_launch(void* const* d_in, const int* in_sizes, int n_in,
                              void* d_out, int out_size) {
    const float* x   = (const float*)d_in[0];
    const void*  ei  = d_in[1];
    const float* W1  = (const float*)d_in[2];
    const float* a1s = (const float*)d_in[3];
    const float* a1d = (const float*)d_in[4];
    const float* b1  = (const float*)d_in[5];
    const float* W2  = (const float*)d_in[6];
    const float* a2s = (const float*)d_in[7];
    const float* a2d = (const float*)d_in[8];
    const float* b2  = (const float*)d_in[9];
    float* out = (float*)d_out;

    const int TB = 256;
    const int gNodes = (NN + 31) / 32;
    const int gEdge2 = (ET / 2 + TB - 1) / TB;
    const int gN     = (NN + TB - 1) / TB;
    const int gGat   = (NN + 7) / 8;            // 8 nodes (warps) per block

    void* cntp;
    cudaGetSymbolAddress(&cntp, g_cnt);

    // fork: layer-1 GEMM concurrent with CSR build
    cudaEventRecord(g_evF, 0);
    cudaStreamWaitEvent(g_s2, g_evF, 0);
    gemm_alpha<128, false><<<gNodes, 512, 0, g_s2>>>(x, W1, a1s, a1d);

    detect_dtype<<<1, 256>>>((const int*)ei);
    cudaMemsetAsync(cntp, 0, NN * sizeof(int), 0);
    hist2<<<gEdge2, TB>>>(ei);
    scan_block<<<NBLK, SCAN_B>>>();
    scan_tops<<<1, 64>>>();
    scan_add<<<gN, TB>>>();
    scatter2<<<gEdge2, TB>>>(ei);

    cudaEventRecord(g_evJ, g_s2);
    cudaStreamWaitEvent(0, g_evJ, 0);

    // ---- layer 1 ----
    gat_node<false><<<gGat, TB>>>(b1, nullptr);

    // ---- layer 2 ----
    gemm_alpha<64, true><<<gNodes, 512>>>(nullptr, W2, a2s, a2d);
    gat_node<true><<<gGat, TB>>>(b2, out);
}